// round 9
// baseline (speedup 1.0000x reference)
#include <cuda_runtime.h>
#include <cuda_bf16.h>
#include <cstdint>
#include <cstddef>

#define D 128
#define NMAX 100096   // multiple of 128
#define EMAX 800000
#define PITCH 68      // u32 per smem row (136 bf16), conflict-free fragments

// ---------------- scratch (device globals; no allocation allowed) ----------------
__device__ __align__(128) float    g_degO[NMAX];
__device__ __align__(128) float    g_degI[NMAX];
__device__ __align__(128) int      g_cntO[NMAX];
__device__ __align__(128) int      g_cntI[NMAX];
__device__ __align__(128) int      g_scan[NMAX];
__device__ __align__(128) int      g_bsum[512];
__device__ __align__(128) int      g_off[NMAX + 1];
__device__ __align__(128) int      g_cur[NMAX];
__device__ __align__(128) int      g_csrc[EMAX];
__device__ __align__(128) float    g_h[(size_t)NMAX * D];   // layer-1 output (fp32)
__device__ __align__(128) uint32_t g_w1hi[D * 64];
__device__ __align__(128) uint32_t g_w1lo[D * 64];
__device__ __align__(128) uint32_t g_w2hi[D * 64];
__device__ __align__(128) uint32_t g_w2lo[D * 64];
__device__ __align__(128) int      g_edges[2 * EMAX];
__device__ int g_is64;

// ---------------- dtype probe ----------------
__global__ void k_detect(const void* __restrict__ ei, int n) {
    const long long* e64 = (const long long*)ei;
    int ok = 1;
    for (int i = 0; i < 16; i++) {
        long long v = e64[i];
        if (v < 0 || v >= (long long)n) ok = 0;
    }
    g_is64 = ok;  // int32 read as int64 -> high word random -> out of range
}

// ---------------- fused convert + degree count ----------------
__global__ void k_convert_count(const void* __restrict__ ei, int E) {
    int i = blockIdx.x * blockDim.x + threadIdx.x;
    if (i >= 2 * E) return;
    int v = g_is64 ? (int)((const long long*)ei)[i] : ((const int*)ei)[i];
    g_edges[i] = v;
    if (i < E) atomicAdd(&g_cntO[v], 1);   // rows
    else       atomicAdd(&g_cntI[v], 1);   // cols
}

__global__ void k_zero_cnt(int n) {
    int i = blockIdx.x * blockDim.x + threadIdx.x;
    if (i < n) { g_cntO[i] = 0; g_cntI[i] = 0; }
}

__global__ void k_finalize_deg(int n) {
    int i = blockIdx.x * blockDim.x + threadIdx.x;
    if (i >= n) return;
    g_degO[i] = rsqrtf((float)max(g_cntO[i], 1));
    g_degI[i] = rsqrtf((float)max(g_cntI[i], 1));
}

// ---------------- W split prep: fp32 -> packed bf16 hi/lo ----------------
__global__ void k_splitw(const float* __restrict__ W1, const float* __restrict__ W2) {
    int i = blockIdx.x * blockDim.x + threadIdx.x;
    if (i >= 2 * D * 64) return;
    int which = i >= D * 64;
    int idx = which ? i - D * 64 : i;
    const float* W = which ? W2 : W1;
    float2 v = reinterpret_cast<const float2*>(W)[idx];
    __nv_bfloat162 h = __float22bfloat162_rn(make_float2(v.x, v.y));
    float lx = v.x - __bfloat162float(h.x);
    float ly = v.y - __bfloat162float(h.y);
    __nv_bfloat162 l = __float22bfloat162_rn(make_float2(lx, ly));
    uint32_t* hi = which ? g_w2hi : g_w1hi;
    uint32_t* lo = which ? g_w2lo : g_w1lo;
    hi[idx] = *reinterpret_cast<uint32_t*>(&h);
    lo[idx] = *reinterpret_cast<uint32_t*>(&l);
}

// ---------------- CSR scan + bucket ----------------
__global__ void k_scan1(int n) {
    __shared__ int s[256];
    int i = blockIdx.x * 256 + threadIdx.x;
    s[threadIdx.x] = (i < n) ? g_cntI[i] : 0;
    __syncthreads();
#pragma unroll
    for (int off = 1; off < 256; off <<= 1) {
        int t = (threadIdx.x >= off) ? s[threadIdx.x - off] : 0;
        __syncthreads();
        s[threadIdx.x] += t;
        __syncthreads();
    }
    if (i < n) g_scan[i] = s[threadIdx.x];
    if (threadIdx.x == 255) g_bsum[blockIdx.x] = s[255];
}
__global__ void k_scan2(int nb) {
    __shared__ int s[512];
    int t = threadIdx.x;
    s[t] = (t < nb) ? g_bsum[t] : 0;
    __syncthreads();
#pragma unroll
    for (int off = 1; off < 512; off <<= 1) {
        int v = (t >= off) ? s[t - off] : 0;
        __syncthreads();
        s[t] += v;
        __syncthreads();
    }
    if (t < nb) g_bsum[t] = (t == 0) ? 0 : s[t - 1];
}
__global__ void k_scan3(int n, int E) {
    int i = blockIdx.x * 256 + threadIdx.x;
    if (i < n) {
        int off = g_bsum[blockIdx.x] + g_scan[i] - g_cntI[i];
        g_off[i] = off;
        g_cur[i] = off;
    }
    if (i == 0) g_off[n] = E;
}
__global__ void k_bucket(int E) {
    int e = blockIdx.x * blockDim.x + threadIdx.x;
    if (e >= E) return;
    int pos = atomicAdd(&g_cur[g_edges[E + e]], 1);
    g_csrc[pos] = g_edges[e];
}

// ================= fused gather + bf16 split-3 MMA GEMM, 512 threads =============
// Phase 1: 16 warps gather 8 dest-nodes each (CSR, fp32 accum) -> smem A (bf16 hi/lo)
//          plus straight copies of pre-split W into smem.
// Phase 2: mma.m16n8k16 split-3 (hi*hi + lo*hi + hi*lo), fp32 accumulate.
// Epilogue: +bias, *invdegI, [+x residual, relu] -> h or out.

__device__ __forceinline__ void mma_bf16(float* d, const uint32_t* a, const uint32_t* b) {
    asm volatile(
        "mma.sync.aligned.m16n8k16.row.col.f32.bf16.bf16.f32 "
        "{%0,%1,%2,%3}, {%4,%5,%6,%7}, {%8,%9}, {%0,%1,%2,%3};"
        : "+f"(d[0]), "+f"(d[1]), "+f"(d[2]), "+f"(d[3])
        : "r"(a[0]), "r"(a[1]), "r"(a[2]), "r"(a[3]), "r"(b[0]), "r"(b[1]));
}

#define SMEM_MMA (4 * 128 * PITCH * 4)   // Ahi, Alo, Whi, Wlo: 139264 B

template <bool LAYER1>
__global__ __launch_bounds__(512, 1)
void k_fused(const float* __restrict__ xin, const float* __restrict__ bias,
             float* __restrict__ outp, int n) {
    extern __shared__ uint32_t sm[];
    uint32_t* Ahi = sm;
    uint32_t* Alo = sm + 128 * PITCH;
    uint32_t* Whi = sm + 2 * 128 * PITCH;
    uint32_t* Wlo = sm + 3 * 128 * PITCH;

    const uint32_t* whi = LAYER1 ? g_w1hi : g_w2hi;
    const uint32_t* wlo = LAYER1 ? g_w1lo : g_w2lo;
    const float* src = LAYER1 ? xin : g_h;

    const int tid = threadIdx.x;
    const int warp = tid >> 5;
    const int lane = tid & 31;
    const int g = lane >> 2;
    const int t = lane & 3;
    const int rowBase = blockIdx.x * 128;
    const int p = warp & 7;        // n-pair
    const int mh = warp >> 3;      // m-half

    // ---- W fill: straight uint4 copies of pre-split weights ----
#pragma unroll
    for (int it = 0; it < 2; it++) {
        int idx = tid + it * 512;            // 0..1023
        int r = idx >> 3;                    // 0..127
        int c = idx & 7;                     // uint4 col (0..7); +8 handled below
        *reinterpret_cast<uint4*>(Whi + r * PITCH + c * 4) =
            reinterpret_cast<const uint4*>(whi + r * 64)[c];
        *reinterpret_cast<uint4*>(Whi + r * PITCH + (c + 8) * 4) =
            reinterpret_cast<const uint4*>(whi + r * 64)[c + 8];
        *reinterpret_cast<uint4*>(Wlo + r * PITCH + c * 4) =
            reinterpret_cast<const uint4*>(wlo + r * 64)[c];
        *reinterpret_cast<uint4*>(Wlo + r * PITCH + (c + 8) * 4) =
            reinterpret_cast<const uint4*>(wlo + r * 64)[c + 8];
    }

    // ---- A gather: warp w owns tile rows [w*8, w*8+8) ----
#pragma unroll
    for (int i = 0; i < 8; i++) {
        int r = warp * 8 + i;
        int v = rowBase + r;
        float4 a0 = make_float4(0.f, 0.f, 0.f, 0.f);
        float4 a1 = make_float4(0.f, 0.f, 0.f, 0.f);
        if (v < n) {
            int q = g_off[v];
            int end = g_off[v + 1];
            for (; q + 1 < end; q += 2) {
                int u0 = g_csrc[q], u1 = g_csrc[q + 1];
                float s0 = g_degO[u0], s1 = g_degO[u1];
                float4 a = reinterpret_cast<const float4*>(src + (size_t)u0 * D)[lane];
                float4 b = reinterpret_cast<const float4*>(src + (size_t)u1 * D)[lane];
                a0.x += a.x * s0; a0.y += a.y * s0; a0.z += a.z * s0; a0.w += a.w * s0;
                a1.x += b.x * s1; a1.y += b.y * s1; a1.z += b.z * s1; a1.w += b.w * s1;
            }
            if (q < end) {
                int u0 = g_csrc[q];
                float s0 = g_degO[u0];
                float4 a = reinterpret_cast<const float4*>(src + (size_t)u0 * D)[lane];
                a0.x += a.x * s0; a0.y += a.y * s0; a0.z += a.z * s0; a0.w += a.w * s0;
            }
            a0.x += a1.x; a0.y += a1.y; a0.z += a1.z; a0.w += a1.w;
        }
        // split to bf16 hi/lo and store to smem
        __nv_bfloat162 h0 = __float22bfloat162_rn(make_float2(a0.x, a0.y));
        __nv_bfloat162 h1 = __float22bfloat162_rn(make_float2(a0.z, a0.w));
        __nv_bfloat162 l0 = __float22bfloat162_rn(make_float2(a0.x - __bfloat162float(h0.x),
                                                              a0.y - __bfloat162float(h0.y)));
        __nv_bfloat162 l1 = __float22bfloat162_rn(make_float2(a0.z - __bfloat162float(h1.x),
                                                              a0.w - __bfloat162float(h1.y)));
        Ahi[r * PITCH + lane * 2]     = *reinterpret_cast<uint32_t*>(&h0);
        Ahi[r * PITCH + lane * 2 + 1] = *reinterpret_cast<uint32_t*>(&h1);
        Alo[r * PITCH + lane * 2]     = *reinterpret_cast<uint32_t*>(&l0);
        Alo[r * PITCH + lane * 2 + 1] = *reinterpret_cast<uint32_t*>(&l1);
    }
    __syncthreads();

    // ---- preload B-hi fragments: this warp's 2 n-tiles, all 8 k-tiles ----
    uint32_t bh[8][2][2];
#pragma unroll
    for (int kt = 0; kt < 8; kt++) {
        int kb = kt * 8;
#pragma unroll
        for (int nt = 0; nt < 2; nt++) {
            int wrow = p * 16 + nt * 8 + g;
            bh[kt][nt][0] = Whi[wrow * PITCH + kb + t];
            bh[kt][nt][1] = Whi[wrow * PITCH + kb + t + 4];
        }
    }

    float acc[4][2][4];
#pragma unroll
    for (int mt = 0; mt < 4; mt++)
#pragma unroll
        for (int nt = 0; nt < 2; nt++)
#pragma unroll
            for (int q = 0; q < 4; q++) acc[mt][nt][q] = 0.f;

#pragma unroll
    for (int kt = 0; kt < 8; kt++) {
        const int kb = kt * 8;
        uint32_t bl[2][2];
#pragma unroll
        for (int nt = 0; nt < 2; nt++) {
            int wrow = p * 16 + nt * 8 + g;
            bl[nt][0] = Wlo[wrow * PITCH + kb + t];
            bl[nt][1] = Wlo[wrow * PITCH + kb + t + 4];
        }
#pragma unroll
        for (int mt = 0; mt < 4; mt++) {
            int r0 = (mh * 64 + mt * 16 + g) * PITCH + kb + t;
            int r1 = (mh * 64 + mt * 16 + g + 8) * PITCH + kb + t;
            uint32_t ah[4], al[4];
            ah[0] = Ahi[r0]; ah[1] = Ahi[r1]; ah[2] = Ahi[r0 + 4]; ah[3] = Ahi[r1 + 4];
            al[0] = Alo[r0]; al[1] = Alo[r1]; al[2] = Alo[r0 + 4]; al[3] = Alo[r1 + 4];
#pragma unroll
            for (int nt = 0; nt < 2; nt++) {
                mma_bf16(acc[mt][nt], ah, bh[kt][nt]);   // hi*hi
                mma_bf16(acc[mt][nt], al, bh[kt][nt]);   // lo*hi
                mma_bf16(acc[mt][nt], ah, bl[nt]);       // hi*lo
            }
        }
    }

    // ---- epilogue ----
    float* out = LAYER1 ? g_h : outp;
#pragma unroll
    for (int nt = 0; nt < 2; nt++) {
        int col = p * 16 + nt * 8 + 2 * t;
        float2 b2 = *reinterpret_cast<const float2*>(bias + col);
#pragma unroll
        for (int mt = 0; mt < 4; mt++) {
            int r0 = rowBase + mh * 64 + mt * 16 + g;
            int r1 = r0 + 8;
            if (r0 < n) {
                float inv = g_degI[r0];
                float o0 = (acc[mt][nt][0] + b2.x) * inv;
                float o1 = (acc[mt][nt][1] + b2.y) * inv;
                if (LAYER1) {
                    float2 x2 = *reinterpret_cast<const float2*>(xin + (size_t)r0 * D + col);
                    o0 = fmaxf(o0 + x2.x, 0.f);
                    o1 = fmaxf(o1 + x2.y, 0.f);
                }
                *reinterpret_cast<float2*>(out + (size_t)r0 * D + col) = make_float2(o0, o1);
            }
            if (r1 < n) {
                float inv = g_degI[r1];
                float o0 = (acc[mt][nt][2] + b2.x) * inv;
                float o1 = (acc[mt][nt][3] + b2.y) * inv;
                if (LAYER1) {
                    float2 x2 = *reinterpret_cast<const float2*>(xin + (size_t)r1 * D + col);
                    o0 = fmaxf(o0 + x2.x, 0.f);
                    o1 = fmaxf(o1 + x2.y, 0.f);
                }
                *reinterpret_cast<float2*>(out + (size_t)r1 * D + col) = make_float2(o0, o1);
            }
        }
    }
}

// ---------------- launch ----------------
extern "C" void kernel_launch(void* const* d_in, const int* in_sizes, int n_in,
                              void* d_out, int out_size) {
    const float* x  = (const float*)d_in[0];
    const void*  ei = d_in[1];
    const float* W1 = (const float*)d_in[2];
    const float* b1 = (const float*)d_in[3];
    const float* W2 = (const float*)d_in[4];
    const float* b2 = (const float*)d_in[5];
    float* out      = (float*)d_out;

    const int n = in_sizes[0] / D;   // 100000
    const int E = in_sizes[1] / 2;   // 800000

    const int CB = (E + 255) / 256;
    const int FB = (n + 255) / 256;
    const int NB = (n + 255) / 256;
    const int GB = (n + 127) / 128;

    cudaFuncSetAttribute(k_fused<true>,  cudaFuncAttributeMaxDynamicSharedMemorySize, SMEM_MMA);
    cudaFuncSetAttribute(k_fused<false>, cudaFuncAttributeMaxDynamicSharedMemorySize, SMEM_MMA);

    // prep
    k_detect<<<1, 1>>>(ei, n);
    k_zero_cnt<<<FB, 256>>>(n);
    k_splitw<<<(2 * D * 64 + 255) / 256, 256>>>(W1, W2);
    k_convert_count<<<(2 * E + 255) / 256, 256>>>(ei, E);
    k_finalize_deg<<<FB, 256>>>(n);
    k_scan1<<<NB, 256>>>(n);
    k_scan2<<<1, 512>>>(NB);
    k_scan3<<<NB, 256>>>(n, E);
    k_bucket<<<CB, 256>>>(E);

    // layer 1: fused gather+gemm; h = relu((agg@W1^T + b1)*invI + x)
    k_fused<true><<<GB, 512, SMEM_MMA>>>(x, b1, nullptr, n);

    // layer 2: fused gather+gemm; out = (agg@W2^T + b2)*invI
    k_fused<false><<<GB, 512, SMEM_MMA>>>(x, b2, out, n);
}

// round 10
// speedup vs baseline: 1.2444x; 1.2444x over previous
#include <cuda_runtime.h>
#include <cuda_bf16.h>
#include <cstdint>
#include <cstddef>

#define D 128
#define NMAX 100096   // multiple of 128
#define EMAX 800000
#define PITCH 68      // u32 per smem row (136 bf16), conflict-free fragments

// ---------------- scratch (device globals; no allocation allowed) ----------------
__device__ __align__(128) float    g_degO[NMAX];
__device__ __align__(128) float    g_degI[NMAX];
__device__ __align__(128) int      g_cntO[NMAX];
__device__ __align__(128) int      g_cntI[NMAX];
__device__ __align__(128) int      g_scan[NMAX];
__device__ __align__(128) int      g_bsum[512];
__device__ __align__(128) int      g_off[NMAX + 1];
__device__ __align__(128) int      g_cur[NMAX];
__device__ __align__(128) int      g_csrc[EMAX];
__device__ __align__(128) uint32_t g_ahi[(size_t)NMAX * 64];  // agg hi (packed bf16x2)
__device__ __align__(128) uint32_t g_alo[(size_t)NMAX * 64];  // agg lo
__device__ __align__(128) float    g_h[(size_t)NMAX * D];     // layer-1 output (fp32)
__device__ __align__(128) uint32_t g_w1hi[D * 64];
__device__ __align__(128) uint32_t g_w1lo[D * 64];
__device__ __align__(128) uint32_t g_w2hi[D * 64];
__device__ __align__(128) uint32_t g_w2lo[D * 64];
__device__ int g_is64;

// ---------------- zero counters + dtype probe (merged) ----------------
__global__ void k_zero_detect(const void* __restrict__ ei, int n) {
    int i = blockIdx.x * blockDim.x + threadIdx.x;
    if (i < n) { g_cntO[i] = 0; g_cntI[i] = 0; }
    if (blockIdx.x == 0 && threadIdx.x == 0) {
        const long long* e64 = (const long long*)ei;
        int ok = 1;
        for (int k = 0; k < 16; k++) {
            long long v = e64[k];
            if (v < 0 || v >= (long long)n) ok = 0;
        }
        g_is64 = ok;   // int32 read as int64 packs random high word -> out of range
    }
}

// ---------------- degree count (reads ei directly) ----------------
__global__ void k_count(const void* __restrict__ ei, int E) {
    int i = blockIdx.x * blockDim.x + threadIdx.x;
    if (i >= 2 * E) return;
    int v = g_is64 ? (int)((const long long*)ei)[i] : ((const int*)ei)[i];
    if (i < E) atomicAdd(&g_cntO[v], 1);
    else       atomicAdd(&g_cntI[v], 1);
}

__global__ void k_finalize_deg(int n) {
    int i = blockIdx.x * blockDim.x + threadIdx.x;
    if (i >= n) return;
    g_degO[i] = rsqrtf((float)max(g_cntO[i], 1));
    g_degI[i] = rsqrtf((float)max(g_cntI[i], 1));
}

// ---------------- W split prep: fp32 -> packed bf16 hi/lo ----------------
__global__ void k_splitw(const float* __restrict__ W1, const float* __restrict__ W2) {
    int i = blockIdx.x * blockDim.x + threadIdx.x;
    if (i >= 2 * D * 64) return;
    int which = i >= D * 64;
    int idx = which ? i - D * 64 : i;
    const float* W = which ? W2 : W1;
    float2 v = reinterpret_cast<const float2*>(W)[idx];
    __nv_bfloat162 h = __float22bfloat162_rn(make_float2(v.x, v.y));
    float lx = v.x - __bfloat162float(h.x);
    float ly = v.y - __bfloat162float(h.y);
    __nv_bfloat162 l = __float22bfloat162_rn(make_float2(lx, ly));
    uint32_t* hi = which ? g_w2hi : g_w1hi;
    uint32_t* lo = which ? g_w2lo : g_w1lo;
    hi[idx] = *reinterpret_cast<uint32_t*>(&h);
    lo[idx] = *reinterpret_cast<uint32_t*>(&l);
}

// ---------------- CSR scan + bucket ----------------
__global__ void k_scan1(int n) {
    __shared__ int s[256];
    int i = blockIdx.x * 256 + threadIdx.x;
    s[threadIdx.x] = (i < n) ? g_cntI[i] : 0;
    __syncthreads();
#pragma unroll
    for (int off = 1; off < 256; off <<= 1) {
        int t = (threadIdx.x >= off) ? s[threadIdx.x - off] : 0;
        __syncthreads();
        s[threadIdx.x] += t;
        __syncthreads();
    }
    if (i < n) g_scan[i] = s[threadIdx.x];
    if (threadIdx.x == 255) g_bsum[blockIdx.x] = s[255];
}
__global__ void k_scan2(int nb) {
    __shared__ int s[512];
    int t = threadIdx.x;
    s[t] = (t < nb) ? g_bsum[t] : 0;
    __syncthreads();
#pragma unroll
    for (int off = 1; off < 512; off <<= 1) {
        int v = (t >= off) ? s[t - off] : 0;
        __syncthreads();
        s[t] += v;
        __syncthreads();
    }
    if (t < nb) g_bsum[t] = (t == 0) ? 0 : s[t - 1];
}
__global__ void k_scan3(int n, int E) {
    int i = blockIdx.x * 256 + threadIdx.x;
    if (i < n) {
        int off = g_bsum[blockIdx.x] + g_scan[i] - g_cntI[i];
        g_off[i] = off;
        g_cur[i] = off;
    }
    if (i == 0) g_off[n] = E;
}
__global__ void k_bucket(const void* __restrict__ ei, int E) {
    int e = blockIdx.x * blockDim.x + threadIdx.x;
    if (e >= E) return;
    int row, col;
    if (g_is64) {
        row = (int)((const long long*)ei)[e];
        col = (int)((const long long*)ei)[(size_t)E + e];
    } else {
        row = ((const int*)ei)[e];
        col = ((const int*)ei)[E + e];
    }
    int pos = atomicAdd(&g_cur[col], 1);
    g_csrc[pos] = row;
}

// ---------------- gather: agg[v] = sum src[u]*invO[u]; writes bf16 hi/lo ----------
// one warp per dest node, 4-edge unroll (MLP=4)
template <bool FROM_H>
__global__ void k_gather(const float* __restrict__ xin, int n) {
    int v = blockIdx.x * (blockDim.x >> 5) + (threadIdx.x >> 5);
    if (v >= n) return;
    int lane = threadIdx.x & 31;
    const float* src = FROM_H ? g_h : xin;
    int p = g_off[v];
    int end = g_off[v + 1];
    float4 a0 = make_float4(0.f, 0.f, 0.f, 0.f);
    float4 a1 = make_float4(0.f, 0.f, 0.f, 0.f);
    for (; p + 3 < end; p += 4) {
        int u0 = g_csrc[p], u1 = g_csrc[p + 1], u2 = g_csrc[p + 2], u3 = g_csrc[p + 3];
        float s0 = g_degO[u0], s1 = g_degO[u1], s2 = g_degO[u2], s3 = g_degO[u3];
        float4 a = reinterpret_cast<const float4*>(src + (size_t)u0 * D)[lane];
        float4 b = reinterpret_cast<const float4*>(src + (size_t)u1 * D)[lane];
        float4 c = reinterpret_cast<const float4*>(src + (size_t)u2 * D)[lane];
        float4 d = reinterpret_cast<const float4*>(src + (size_t)u3 * D)[lane];
        a0.x += a.x * s0; a0.y += a.y * s0; a0.z += a.z * s0; a0.w += a.w * s0;
        a1.x += b.x * s1; a1.y += b.y * s1; a1.z += b.z * s1; a1.w += b.w * s1;
        a0.x += c.x * s2; a0.y += c.y * s2; a0.z += c.z * s2; a0.w += c.w * s2;
        a1.x += d.x * s3; a1.y += d.y * s3; a1.z += d.z * s3; a1.w += d.w * s3;
    }
    for (; p < end; p++) {
        int u0 = g_csrc[p];
        float s0 = g_degO[u0];
        float4 a = reinterpret_cast<const float4*>(src + (size_t)u0 * D)[lane];
        a0.x += a.x * s0; a0.y += a.y * s0; a0.z += a.z * s0; a0.w += a.w * s0;
    }
    a0.x += a1.x; a0.y += a1.y; a0.z += a1.z; a0.w += a1.w;

    __nv_bfloat162 h0 = __float22bfloat162_rn(make_float2(a0.x, a0.y));
    __nv_bfloat162 h1 = __float22bfloat162_rn(make_float2(a0.z, a0.w));
    __nv_bfloat162 l0 = __float22bfloat162_rn(make_float2(a0.x - __bfloat162float(h0.x),
                                                          a0.y - __bfloat162float(h0.y)));
    __nv_bfloat162 l1 = __float22bfloat162_rn(make_float2(a0.z - __bfloat162float(h1.x),
                                                          a0.w - __bfloat162float(h1.y)));
    uint2 hv = make_uint2(*reinterpret_cast<uint32_t*>(&h0), *reinterpret_cast<uint32_t*>(&h1));
    uint2 lv = make_uint2(*reinterpret_cast<uint32_t*>(&l0), *reinterpret_cast<uint32_t*>(&l1));
    reinterpret_cast<uint2*>(g_ahi + (size_t)v * 64)[lane] = hv;
    reinterpret_cast<uint2*>(g_alo + (size_t)v * 64)[lane] = lv;
}

// ================= bf16 split-3 MMA GEMM: 64-row tiles, 2 CTA/SM =================
__device__ __forceinline__ void mma_bf16(float* d, const uint32_t* a, const uint32_t* b) {
    asm volatile(
        "mma.sync.aligned.m16n8k16.row.col.f32.bf16.bf16.f32 "
        "{%0,%1,%2,%3}, {%4,%5,%6,%7}, {%8,%9}, {%0,%1,%2,%3};"
        : "+f"(d[0]), "+f"(d[1]), "+f"(d[2]), "+f"(d[3])
        : "r"(a[0]), "r"(a[1]), "r"(a[2]), "r"(a[3]), "r"(b[0]), "r"(b[1]));
}

// smem: Ahi(64x68) Alo(64x68) Whi(128x68) Wlo(128x68) u32 = 104448 B -> 2 CTA/SM
#define SMEM_MMA ((2 * 64 * PITCH + 2 * 128 * PITCH) * 4)

template <bool LAYER1>
__global__ __launch_bounds__(512, 2)
void k_gemm_mma(const float* __restrict__ bias,
                const float* __restrict__ xres, float* __restrict__ outp, int n) {
    extern __shared__ uint32_t sm[];
    uint32_t* Ahi = sm;
    uint32_t* Alo = sm + 64 * PITCH;
    uint32_t* Whi = sm + 2 * 64 * PITCH;
    uint32_t* Wlo = Whi + 128 * PITCH;

    const uint32_t* whi = LAYER1 ? g_w1hi : g_w2hi;
    const uint32_t* wlo = LAYER1 ? g_w1lo : g_w2lo;

    const int tid = threadIdx.x;
    const int warp = tid >> 5;
    const int lane = tid & 31;
    const int g = lane >> 2;
    const int t = lane & 3;
    const int rowBase = blockIdx.x * 64;
    const int p = warp & 7;        // n-pair (16 cols)
    const int mh = warp >> 3;      // m-half (32 rows)

    // ---- A fill: 64 rows x 16 uint4, hi+lo ----
#pragma unroll
    for (int it = 0; it < 2; it++) {
        int idx = tid + it * 512;            // 0..1023
        int r = idx >> 4, c = idx & 15;
        int grow = rowBase + r;
        uint4 vh = make_uint4(0u, 0u, 0u, 0u), vl = vh;
        if (grow < n) {
            vh = reinterpret_cast<const uint4*>(g_ahi + (size_t)grow * 64)[c];
            vl = reinterpret_cast<const uint4*>(g_alo + (size_t)grow * 64)[c];
        }
        *reinterpret_cast<uint4*>(Ahi + r * PITCH + c * 4) = vh;
        *reinterpret_cast<uint4*>(Alo + r * PITCH + c * 4) = vl;
    }
    // ---- W fill: 128 rows x 16 uint4, hi+lo ----
#pragma unroll
    for (int it = 0; it < 4; it++) {
        int idx = tid + it * 512;            // 0..2047
        int r = idx >> 4, c = idx & 15;
        *reinterpret_cast<uint4*>(Whi + r * PITCH + c * 4) =
            reinterpret_cast<const uint4*>(whi + r * 64)[c];
        *reinterpret_cast<uint4*>(Wlo + r * PITCH + c * 4) =
            reinterpret_cast<const uint4*>(wlo + r * 64)[c];
    }
    __syncthreads();

    float acc[2][2][4];
#pragma unroll
    for (int mt = 0; mt < 2; mt++)
#pragma unroll
        for (int nt = 0; nt < 2; nt++)
#pragma unroll
            for (int q = 0; q < 4; q++) acc[mt][nt][q] = 0.f;

#pragma unroll
    for (int kt = 0; kt < 8; kt++) {
        const int kb = kt * 8;
        uint32_t bh[2][2], bl[2][2];
#pragma unroll
        for (int nt = 0; nt < 2; nt++) {
            int wrow = p * 16 + nt * 8 + g;
            bh[nt][0] = Whi[wrow * PITCH + kb + t];
            bh[nt][1] = Whi[wrow * PITCH + kb + t + 4];
            bl[nt][0] = Wlo[wrow * PITCH + kb + t];
            bl[nt][1] = Wlo[wrow * PITCH + kb + t + 4];
        }
#pragma unroll
        for (int mt = 0; mt < 2; mt++) {
            int r0 = (mh * 32 + mt * 16 + g) * PITCH + kb + t;
            int r1 = (mh * 32 + mt * 16 + g + 8) * PITCH + kb + t;
            uint32_t ah[4], al[4];
            ah[0] = Ahi[r0]; ah[1] = Ahi[r1]; ah[2] = Ahi[r0 + 4]; ah[3] = Ahi[r1 + 4];
            al[0] = Alo[r0]; al[1] = Alo[r1]; al[2] = Alo[r0 + 4]; al[3] = Alo[r1 + 4];
#pragma unroll
            for (int nt = 0; nt < 2; nt++) {
                mma_bf16(acc[mt][nt], ah, bh[nt]);   // hi*hi
                mma_bf16(acc[mt][nt], al, bh[nt]);   // lo*hi
                mma_bf16(acc[mt][nt], ah, bl[nt]);   // hi*lo
            }
        }
    }

    // ---- epilogue ----
    float* out = LAYER1 ? g_h : outp;
#pragma unroll
    for (int nt = 0; nt < 2; nt++) {
        int col = p * 16 + nt * 8 + 2 * t;
        float2 b2 = *reinterpret_cast<const float2*>(bias + col);
#pragma unroll
        for (int mt = 0; mt < 2; mt++) {
            int r0 = rowBase + mh * 32 + mt * 16 + g;
            int r1 = r0 + 8;
            if (r0 < n) {
                float inv = g_degI[r0];
                float o0 = (acc[mt][nt][0] + b2.x) * inv;
                float o1 = (acc[mt][nt][1] + b2.y) * inv;
                if (LAYER1) {
                    float2 x2 = *reinterpret_cast<const float2*>(xres + (size_t)r0 * D + col);
                    o0 = fmaxf(o0 + x2.x, 0.f);
                    o1 = fmaxf(o1 + x2.y, 0.f);
                }
                *reinterpret_cast<float2*>(out + (size_t)r0 * D + col) = make_float2(o0, o1);
            }
            if (r1 < n) {
                float inv = g_degI[r1];
                float o0 = (acc[mt][nt][2] + b2.x) * inv;
                float o1 = (acc[mt][nt][3] + b2.y) * inv;
                if (LAYER1) {
                    float2 x2 = *reinterpret_cast<const float2*>(xres + (size_t)r1 * D + col);
                    o0 = fmaxf(o0 + x2.x, 0.f);
                    o1 = fmaxf(o1 + x2.y, 0.f);
                }
                *reinterpret_cast<float2*>(out + (size_t)r1 * D + col) = make_float2(o0, o1);
            }
        }
    }
}

// ---------------- launch ----------------
extern "C" void kernel_launch(void* const* d_in, const int* in_sizes, int n_in,
                              void* d_out, int out_size) {
    const float* x  = (const float*)d_in[0];
    const void*  ei = d_in[1];
    const float* W1 = (const float*)d_in[2];
    const float* b1 = (const float*)d_in[3];
    const float* W2 = (const float*)d_in[4];
    const float* b2 = (const float*)d_in[5];
    float* out      = (float*)d_out;

    const int n = in_sizes[0] / D;   // 100000
    const int E = in_sizes[1] / 2;   // 800000

    const int CB = (E + 255) / 256;
    const int FB = (n + 255) / 256;
    const int NB = (n + 255) / 256;
    const int GAB = (n + 7) / 8;
    const int GB = (n + 63) / 64;

    cudaFuncSetAttribute(k_gemm_mma<true>,  cudaFuncAttributeMaxDynamicSharedMemorySize, SMEM_MMA);
    cudaFuncSetAttribute(k_gemm_mma<false>, cudaFuncAttributeMaxDynamicSharedMemorySize, SMEM_MMA);

    // prep
    k_zero_detect<<<FB, 256>>>(ei, n);
    k_splitw<<<(2 * D * 64 + 255) / 256, 256>>>(W1, W2);
    k_count<<<(2 * E + 255) / 256, 256>>>(ei, E);
    k_finalize_deg<<<FB, 256>>>(n);
    k_scan1<<<NB, 256>>>(n);
    k_scan2<<<1, 512>>>(NB);
    k_scan3<<<NB, 256>>>(n, E);
    k_bucket<<<CB, 256>>>(ei, E);

    // layer 1: gather -> (ahi, alo); h = relu((agg@W1^T + b1)*invI + x)
    k_gather<false><<<GAB, 256>>>(x, n);
    k_gemm_mma<true><<<GB, 512, SMEM_MMA>>>(b1, x, nullptr, n);

    // layer 2: gather(h) -> (ahi, alo); out = (agg@W2^T + b2)*invI
    k_gather<true><<<GAB, 256>>>(nullptr, n);
    k_gemm_mma<false><<<GB, 512, SMEM_MMA>>>(b2, nullptr, out, n);
}

// round 11
// speedup vs baseline: 1.2566x; 1.0098x over previous
#include <cuda_runtime.h>
#include <cuda_bf16.h>
#include <cstdint>
#include <cstddef>

#define D 128
#define NMAX 100096   // multiple of 128
#define EMAX 800000
#define PITCH 68      // u32 per smem row (136 bf16), conflict-free fragments

// ---------------- scratch (device globals; no allocation allowed) ----------------
__device__ __align__(128) float    g_degO[NMAX];
__device__ __align__(128) float    g_degI[NMAX];
__device__ __align__(128) int      g_cntO[NMAX];
__device__ __align__(128) int      g_cntI[NMAX];
__device__ __align__(128) int      g_scan[NMAX];
__device__ __align__(128) int      g_bsum[512];
__device__ __align__(128) int      g_off[NMAX + 1];
__device__ __align__(128) int      g_cur[NMAX];
__device__ __align__(128) int      g_csrc[EMAX];
__device__ __align__(128) uint32_t g_ahi[(size_t)NMAX * 64];  // agg hi (packed bf16x2)
__device__ __align__(128) uint32_t g_alo[(size_t)NMAX * 64];  // agg lo
__device__ __align__(128) float    g_h[(size_t)NMAX * D];     // layer-1 output (fp32)
__device__ __align__(128) uint32_t g_w1hi[D * 64];
__device__ __align__(128) uint32_t g_w1lo[D * 64];
__device__ __align__(128) uint32_t g_w2hi[D * 64];
__device__ __align__(128) uint32_t g_w2lo[D * 64];
__device__ int g_is64;

// ---------------- prep0: zero counters + dtype probe + W split (one grid) --------
// blocks [0, FB): zero cnt arrays (+ block 0 thread 0 runs the dtype probe)
// blocks [FB, FB+64): split W1/W2 fp32 -> packed bf16 hi/lo (16384 u32 granules)
__global__ void k_prep0(const void* __restrict__ ei, int n, int FB,
                        const float* __restrict__ W1, const float* __restrict__ W2) {
    if (blockIdx.x < (unsigned)FB) {
        int i = blockIdx.x * blockDim.x + threadIdx.x;
        if (i < n) { g_cntO[i] = 0; g_cntI[i] = 0; }
        if (blockIdx.x == 0 && threadIdx.x == 0) {
            const long long* e64 = (const long long*)ei;
            int ok = 1;
            for (int k = 0; k < 16; k++) {
                long long v = e64[k];
                if (v < 0 || v >= (long long)n) ok = 0;
            }
            g_is64 = ok;   // int32 read as int64 packs random high word -> out of range
        }
    } else {
        int i = (blockIdx.x - FB) * blockDim.x + threadIdx.x;  // 0..16383
        if (i >= 2 * D * 64) return;
        int which = i >= D * 64;
        int idx = which ? i - D * 64 : i;
        const float* W = which ? W2 : W1;
        float2 v = reinterpret_cast<const float2*>(W)[idx];
        __nv_bfloat162 h = __float22bfloat162_rn(make_float2(v.x, v.y));
        float lx = v.x - __bfloat162float(h.x);
        float ly = v.y - __bfloat162float(h.y);
        __nv_bfloat162 l = __float22bfloat162_rn(make_float2(lx, ly));
        uint32_t* hi = which ? g_w2hi : g_w1hi;
        uint32_t* lo = which ? g_w2lo : g_w1lo;
        hi[idx] = *reinterpret_cast<uint32_t*>(&h);
        lo[idx] = *reinterpret_cast<uint32_t*>(&l);
    }
}

// ---------------- degree count (reads ei directly) ----------------
__global__ void k_count(const void* __restrict__ ei, int E) {
    int i = blockIdx.x * blockDim.x + threadIdx.x;
    if (i >= 2 * E) return;
    int v = g_is64 ? (int)((const long long*)ei)[i] : ((const int*)ei)[i];
    if (i < E) atomicAdd(&g_cntO[v], 1);
    else       atomicAdd(&g_cntI[v], 1);
}

// ---------------- CSR scan (+ finalize degrees in scan3) ----------------
__global__ void k_scan1(int n) {
    __shared__ int s[256];
    int i = blockIdx.x * 256 + threadIdx.x;
    s[threadIdx.x] = (i < n) ? g_cntI[i] : 0;
    __syncthreads();
#pragma unroll
    for (int off = 1; off < 256; off <<= 1) {
        int t = (threadIdx.x >= off) ? s[threadIdx.x - off] : 0;
        __syncthreads();
        s[threadIdx.x] += t;
        __syncthreads();
    }
    if (i < n) g_scan[i] = s[threadIdx.x];
    if (threadIdx.x == 255) g_bsum[blockIdx.x] = s[255];
}
__global__ void k_scan2(int nb) {
    __shared__ int s[512];
    int t = threadIdx.x;
    s[t] = (t < nb) ? g_bsum[t] : 0;
    __syncthreads();
#pragma unroll
    for (int off = 1; off < 512; off <<= 1) {
        int v = (t >= off) ? s[t - off] : 0;
        __syncthreads();
        s[t] += v;
        __syncthreads();
    }
    if (t < nb) g_bsum[t] = (t == 0) ? 0 : s[t - 1];
}
__global__ void k_scan3_fin(int n, int E) {
    int i = blockIdx.x * 256 + threadIdx.x;
    if (i < n) {
        int off = g_bsum[blockIdx.x] + g_scan[i] - g_cntI[i];
        g_off[i] = off;
        g_cur[i] = off;
        g_degO[i] = rsqrtf((float)max(g_cntO[i], 1));
        g_degI[i] = rsqrtf((float)max(g_cntI[i], 1));
    }
    if (i == 0) g_off[n] = E;
}
__global__ void k_bucket(const void* __restrict__ ei, int E) {
    int e = blockIdx.x * blockDim.x + threadIdx.x;
    if (e >= E) return;
    int row, col;
    if (g_is64) {
        row = (int)((const long long*)ei)[e];
        col = (int)((const long long*)ei)[(size_t)E + e];
    } else {
        row = ((const int*)ei)[e];
        col = ((const int*)ei)[E + e];
    }
    int pos = atomicAdd(&g_cur[col], 1);
    g_csrc[pos] = row;
}

// ---------------- gather: agg[v] = sum src[u]*invO[u]; writes bf16 hi/lo ----------
template <bool FROM_H>
__global__ void k_gather(const float* __restrict__ xin, int n) {
    int v = blockIdx.x * (blockDim.x >> 5) + (threadIdx.x >> 5);
    if (v >= n) return;
    int lane = threadIdx.x & 31;
    const float* src = FROM_H ? g_h : xin;
    int p = g_off[v];
    int end = g_off[v + 1];
    float4 a0 = make_float4(0.f, 0.f, 0.f, 0.f);
    float4 a1 = make_float4(0.f, 0.f, 0.f, 0.f);
    for (; p + 3 < end; p += 4) {
        int u0 = g_csrc[p], u1 = g_csrc[p + 1], u2 = g_csrc[p + 2], u3 = g_csrc[p + 3];
        float s0 = g_degO[u0], s1 = g_degO[u1], s2 = g_degO[u2], s3 = g_degO[u3];
        float4 a = reinterpret_cast<const float4*>(src + (size_t)u0 * D)[lane];
        float4 b = reinterpret_cast<const float4*>(src + (size_t)u1 * D)[lane];
        float4 c = reinterpret_cast<const float4*>(src + (size_t)u2 * D)[lane];
        float4 d = reinterpret_cast<const float4*>(src + (size_t)u3 * D)[lane];
        a0.x += a.x * s0; a0.y += a.y * s0; a0.z += a.z * s0; a0.w += a.w * s0;
        a1.x += b.x * s1; a1.y += b.y * s1; a1.z += b.z * s1; a1.w += b.w * s1;
        a0.x += c.x * s2; a0.y += c.y * s2; a0.z += c.z * s2; a0.w += c.w * s2;
        a1.x += d.x * s3; a1.y += d.y * s3; a1.z += d.z * s3; a1.w += d.w * s3;
    }
    for (; p < end; p++) {
        int u0 = g_csrc[p];
        float s0 = g_degO[u0];
        float4 a = reinterpret_cast<const float4*>(src + (size_t)u0 * D)[lane];
        a0.x += a.x * s0; a0.y += a.y * s0; a0.z += a.z * s0; a0.w += a.w * s0;
    }
    a0.x += a1.x; a0.y += a1.y; a0.z += a1.z; a0.w += a1.w;

    __nv_bfloat162 h0 = __float22bfloat162_rn(make_float2(a0.x, a0.y));
    __nv_bfloat162 h1 = __float22bfloat162_rn(make_float2(a0.z, a0.w));
    __nv_bfloat162 l0 = __float22bfloat162_rn(make_float2(a0.x - __bfloat162float(h0.x),
                                                          a0.y - __bfloat162float(h0.y)));
    __nv_bfloat162 l1 = __float22bfloat162_rn(make_float2(a0.z - __bfloat162float(h1.x),
                                                          a0.w - __bfloat162float(h1.y)));
    uint2 hv = make_uint2(*reinterpret_cast<uint32_t*>(&h0), *reinterpret_cast<uint32_t*>(&h1));
    uint2 lv = make_uint2(*reinterpret_cast<uint32_t*>(&l0), *reinterpret_cast<uint32_t*>(&l1));
    reinterpret_cast<uint2*>(g_ahi + (size_t)v * 64)[lane] = hv;
    reinterpret_cast<uint2*>(g_alo + (size_t)v * 64)[lane] = lv;
}

// ================= bf16 split-3 MMA GEMM: 2x 64-row tiles per CTA, 2 CTA/SM ======
__device__ __forceinline__ void mma_bf16(float* d, const uint32_t* a, const uint32_t* b) {
    asm volatile(
        "mma.sync.aligned.m16n8k16.row.col.f32.bf16.bf16.f32 "
        "{%0,%1,%2,%3}, {%4,%5,%6,%7}, {%8,%9}, {%0,%1,%2,%3};"
        : "+f"(d[0]), "+f"(d[1]), "+f"(d[2]), "+f"(d[3])
        : "r"(a[0]), "r"(a[1]), "r"(a[2]), "r"(a[3]), "r"(b[0]), "r"(b[1]));
}

// smem: Ahi(64x68) Alo(64x68) Whi(128x68) Wlo(128x68) u32 = 104448 B -> 2 CTA/SM
#define SMEM_MMA ((2 * 64 * PITCH + 2 * 128 * PITCH) * 4)

template <bool LAYER1>
__global__ __launch_bounds__(512, 2)
void k_gemm_mma(const float* __restrict__ bias,
                const float* __restrict__ xres, float* __restrict__ outp, int n) {
    extern __shared__ uint32_t sm[];
    uint32_t* Ahi = sm;
    uint32_t* Alo = sm + 64 * PITCH;
    uint32_t* Whi = sm + 2 * 64 * PITCH;
    uint32_t* Wlo = Whi + 128 * PITCH;

    const uint32_t* whi = LAYER1 ? g_w1hi : g_w2hi;
    const uint32_t* wlo = LAYER1 ? g_w1lo : g_w2lo;

    const int tid = threadIdx.x;
    const int warp = tid >> 5;
    const int lane = tid & 31;
    const int g = lane >> 2;
    const int t = lane & 3;
    const int p = warp & 7;        // n-pair (16 cols)
    const int mh = warp >> 3;      // m-half (32 rows)
    float* out = LAYER1 ? g_h : outp;

    // ---- W fill once: 128 rows x 16 uint4, hi+lo ----
#pragma unroll
    for (int it = 0; it < 4; it++) {
        int idx = tid + it * 512;            // 0..2047
        int r = idx >> 4, c = idx & 15;
        *reinterpret_cast<uint4*>(Whi + r * PITCH + c * 4) =
            reinterpret_cast<const uint4*>(whi + r * 64)[c];
        *reinterpret_cast<uint4*>(Wlo + r * PITCH + c * 4) =
            reinterpret_cast<const uint4*>(wlo + r * 64)[c];
    }

    // ---- two 64-row tiles per CTA ----
#pragma unroll
    for (int tile = 0; tile < 2; tile++) {
        const int rowBase = blockIdx.x * 128 + tile * 64;

        // A fill: 64 rows x 16 uint4, hi+lo
#pragma unroll
        for (int it = 0; it < 2; it++) {
            int idx = tid + it * 512;        // 0..1023
            int r = idx >> 4, c = idx & 15;
            int grow = rowBase + r;
            uint4 vh = make_uint4(0u, 0u, 0u, 0u), vl = vh;
            if (grow < n) {
                vh = reinterpret_cast<const uint4*>(g_ahi + (size_t)grow * 64)[c];
                vl = reinterpret_cast<const uint4*>(g_alo + (size_t)grow * 64)[c];
            }
            *reinterpret_cast<uint4*>(Ahi + r * PITCH + c * 4) = vh;
            *reinterpret_cast<uint4*>(Alo + r * PITCH + c * 4) = vl;
        }
        __syncthreads();

        float acc[2][2][4];
#pragma unroll
        for (int mt = 0; mt < 2; mt++)
#pragma unroll
            for (int nt = 0; nt < 2; nt++)
#pragma unroll
                for (int q = 0; q < 4; q++) acc[mt][nt][q] = 0.f;

#pragma unroll
        for (int kt = 0; kt < 8; kt++) {
            const int kb = kt * 8;
            uint32_t bh[2][2], bl[2][2];
#pragma unroll
            for (int nt = 0; nt < 2; nt++) {
                int wrow = p * 16 + nt * 8 + g;
                bh[nt][0] = Whi[wrow * PITCH + kb + t];
                bh[nt][1] = Whi[wrow * PITCH + kb + t + 4];
                bl[nt][0] = Wlo[wrow * PITCH + kb + t];
                bl[nt][1] = Wlo[wrow * PITCH + kb + t + 4];
            }
#pragma unroll
            for (int mt = 0; mt < 2; mt++) {
                int r0 = (mh * 32 + mt * 16 + g) * PITCH + kb + t;
                int r1 = (mh * 32 + mt * 16 + g + 8) * PITCH + kb + t;
                uint32_t ah[4], al[4];
                ah[0] = Ahi[r0]; ah[1] = Ahi[r1]; ah[2] = Ahi[r0 + 4]; ah[3] = Ahi[r1 + 4];
                al[0] = Alo[r0]; al[1] = Alo[r1]; al[2] = Alo[r0 + 4]; al[3] = Alo[r1 + 4];
#pragma unroll
                for (int nt = 0; nt < 2; nt++) {
                    mma_bf16(acc[mt][nt], ah, bh[nt]);   // hi*hi
                    mma_bf16(acc[mt][nt], al, bh[nt]);   // lo*hi
                    mma_bf16(acc[mt][nt], ah, bl[nt]);   // hi*lo
                }
            }
        }
        __syncthreads();   // A-tile fully consumed before next fill

        // epilogue for this tile
#pragma unroll
        for (int nt = 0; nt < 2; nt++) {
            int col = p * 16 + nt * 8 + 2 * t;
            float2 b2 = *reinterpret_cast<const float2*>(bias + col);
#pragma unroll
            for (int mt = 0; mt < 2; mt++) {
                int r0 = rowBase + mh * 32 + mt * 16 + g;
                int r1 = r0 + 8;
                if (r0 < n) {
                    float inv = g_degI[r0];
                    float o0 = (acc[mt][nt][0] + b2.x) * inv;
                    float o1 = (acc[mt][nt][1] + b2.y) * inv;
                    if (LAYER1) {
                        float2 x2 = *reinterpret_cast<const float2*>(xres + (size_t)r0 * D + col);
                        o0 = fmaxf(o0 + x2.x, 0.f);
                        o1 = fmaxf(o1 + x2.y, 0.f);
                    }
                    *reinterpret_cast<float2*>(out + (size_t)r0 * D + col) = make_float2(o0, o1);
                }
                if (r1 < n) {
                    float inv = g_degI[r1];
                    float o0 = (acc[mt][nt][2] + b2.x) * inv;
                    float o1 = (acc[mt][nt][3] + b2.y) * inv;
                    if (LAYER1) {
                        float2 x2 = *reinterpret_cast<const float2*>(xres + (size_t)r1 * D + col);
                        o0 = fmaxf(o0 + x2.x, 0.f);
                        o1 = fmaxf(o1 + x2.y, 0.f);
                    }
                    *reinterpret_cast<float2*>(out + (size_t)r1 * D + col) = make_float2(o0, o1);
                }
            }
        }
    }
}

// ---------------- launch ----------------
extern "C" void kernel_launch(void* const* d_in, const int* in_sizes, int n_in,
                              void* d_out, int out_size) {
    const float* x  = (const float*)d_in[0];
    const void*  ei = d_in[1];
    const float* W1 = (const float*)d_in[2];
    const float* b1 = (const float*)d_in[3];
    const float* W2 = (const float*)d_in[4];
    const float* b2 = (const float*)d_in[5];
    float* out      = (float*)d_out;

    const int n = in_sizes[0] / D;   // 100000
    const int E = in_sizes[1] / 2;   // 800000

    const int CB = (E + 255) / 256;
    const int FB = (n + 255) / 256;
    const int NB = (n + 255) / 256;
    const int GAB = (n + 7) / 8;
    const int GB = (n + 127) / 128;

    cudaFuncSetAttribute(k_gemm_mma<true>,  cudaFuncAttributeMaxDynamicSharedMemorySize, SMEM_MMA);
    cudaFuncSetAttribute(k_gemm_mma<false>, cudaFuncAttributeMaxDynamicSharedMemorySize, SMEM_MMA);

    // prep (6 launches)
    k_prep0<<<FB + 64, 256>>>(ei, n, FB, W1, W2);
    k_count<<<(2 * E + 255) / 256, 256>>>(ei, E);
    k_scan1<<<NB, 256>>>(n);
    k_scan2<<<1, 512>>>(NB);
    k_scan3_fin<<<NB, 256>>>(n, E);
    k_bucket<<<CB, 256>>>(ei, E);

    // layer 1: gather -> (ahi, alo); h = relu((agg@W1^T + b1)*invI + x)
    k_gather<false><<<GAB, 256>>>(x, n);
    k_gemm_mma<true><<<GB, 512, SMEM_MMA>>>(b1, x, nullptr, n);

    // layer 2: gather(h) -> (ahi, alo); out = (agg@W2^T + b2)*invI
    k_gather<true><<<GAB, 256>>>(nullptr, n);
    k_gemm_mma<false><<<GB, 512, SMEM_MMA>>>(b2, nullptr, out, n);
}

// round 12
// speedup vs baseline: 1.3015x; 1.0357x over previous
#include <cuda_runtime.h>
#include <cuda_bf16.h>
#include <cstdint>
#include <cstddef>

#define D 128
#define NMAX 100096   // multiple of 128
#define EMAX 800000
#define PITCH 68      // u32 per smem row (136 bf16): ldmatrix conflict-free

// ---------------- scratch (device globals; no allocation allowed) ----------------
__device__ __align__(128) float    g_degO[NMAX];
__device__ __align__(128) float    g_degI[NMAX];
__device__ __align__(128) int      g_cntO[NMAX];
__device__ __align__(128) int      g_cntI[NMAX];
__device__ __align__(128) int      g_scan[NMAX];
__device__ __align__(128) int      g_bsum[512];
__device__ __align__(128) int      g_off[NMAX + 1];
__device__ __align__(128) int      g_cur[NMAX];
__device__ __align__(128) int      g_csrc[EMAX];
__device__ __align__(128) uint32_t g_ahi[(size_t)NMAX * 64];  // agg hi (packed bf16x2)
__device__ __align__(128) uint32_t g_alo[(size_t)NMAX * 64];  // agg lo
__device__ __align__(128) float    g_h[(size_t)NMAX * D];     // layer-1 output (fp32)
__device__ __align__(128) uint32_t g_w1hi[D * 64];
__device__ __align__(128) uint32_t g_w1lo[D * 64];
__device__ __align__(128) uint32_t g_w2hi[D * 64];
__device__ __align__(128) uint32_t g_w2lo[D * 64];
__device__ int g_is64;

// ---------------- prep0: zero counters + dtype probe + W split (one grid) --------
__global__ void k_prep0(const void* __restrict__ ei, int n, int FB,
                        const float* __restrict__ W1, const float* __restrict__ W2) {
    if (blockIdx.x < (unsigned)FB) {
        int i = blockIdx.x * blockDim.x + threadIdx.x;
        if (i < n) { g_cntO[i] = 0; g_cntI[i] = 0; }
        if (blockIdx.x == 0 && threadIdx.x == 0) {
            const long long* e64 = (const long long*)ei;
            int ok = 1;
            for (int k = 0; k < 16; k++) {
                long long v = e64[k];
                if (v < 0 || v >= (long long)n) ok = 0;
            }
            g_is64 = ok;   // int32 read as int64 packs random high word -> out of range
        }
    } else {
        int i = (blockIdx.x - FB) * blockDim.x + threadIdx.x;  // 0..16383
        if (i >= 2 * D * 64) return;
        int which = i >= D * 64;
        int idx = which ? i - D * 64 : i;
        const float* W = which ? W2 : W1;
        float2 v = reinterpret_cast<const float2*>(W)[idx];
        __nv_bfloat162 h = __float22bfloat162_rn(make_float2(v.x, v.y));
        float lx = v.x - __bfloat162float(h.x);
        float ly = v.y - __bfloat162float(h.y);
        __nv_bfloat162 l = __float22bfloat162_rn(make_float2(lx, ly));
        uint32_t* hi = which ? g_w2hi : g_w1hi;
        uint32_t* lo = which ? g_w2lo : g_w1lo;
        hi[idx] = *reinterpret_cast<uint32_t*>(&h);
        lo[idx] = *reinterpret_cast<uint32_t*>(&l);
    }
}

// ---------------- degree count (reads ei directly) ----------------
__global__ void k_count(const void* __restrict__ ei, int E) {
    int i = blockIdx.x * blockDim.x + threadIdx.x;
    if (i >= 2 * E) return;
    int v = g_is64 ? (int)((const long long*)ei)[i] : ((const int*)ei)[i];
    if (i < E) atomicAdd(&g_cntO[v], 1);
    else       atomicAdd(&g_cntI[v], 1);
}

// ---------------- CSR scan (+ finalize degrees in scan3) ----------------
__global__ void k_scan1(int n) {
    __shared__ int s[256];
    int i = blockIdx.x * 256 + threadIdx.x;
    s[threadIdx.x] = (i < n) ? g_cntI[i] : 0;
    __syncthreads();
#pragma unroll
    for (int off = 1; off < 256; off <<= 1) {
        int t = (threadIdx.x >= off) ? s[threadIdx.x - off] : 0;
        __syncthreads();
        s[threadIdx.x] += t;
        __syncthreads();
    }
    if (i < n) g_scan[i] = s[threadIdx.x];
    if (threadIdx.x == 255) g_bsum[blockIdx.x] = s[255];
}
__global__ void k_scan2(int nb) {
    __shared__ int s[512];
    int t = threadIdx.x;
    s[t] = (t < nb) ? g_bsum[t] : 0;
    __syncthreads();
#pragma unroll
    for (int off = 1; off < 512; off <<= 1) {
        int v = (t >= off) ? s[t - off] : 0;
        __syncthreads();
        s[t] += v;
        __syncthreads();
    }
    if (t < nb) g_bsum[t] = (t == 0) ? 0 : s[t - 1];
}
__global__ void k_scan3_fin(int n, int E) {
    int i = blockIdx.x * 256 + threadIdx.x;
    if (i < n) {
        int off = g_bsum[blockIdx.x] + g_scan[i] - g_cntI[i];
        g_off[i] = off;
        g_cur[i] = off;
        g_degO[i] = rsqrtf((float)max(g_cntO[i], 1));
        g_degI[i] = rsqrtf((float)max(g_cntI[i], 1));
    }
    if (i == 0) g_off[n] = E;
}
__global__ void k_bucket(const void* __restrict__ ei, int E) {
    int e = blockIdx.x * blockDim.x + threadIdx.x;
    if (e >= E) return;
    int row, col;
    if (g_is64) {
        row = (int)((const long long*)ei)[e];
        col = (int)((const long long*)ei)[(size_t)E + e];
    } else {
        row = ((const int*)ei)[e];
        col = ((const int*)ei)[E + e];
    }
    int pos = atomicAdd(&g_cur[col], 1);
    g_csrc[pos] = row;
}

// ---------------- gather: agg[v] = sum src[u]*invO[u]; writes bf16 hi/lo ----------
template <bool FROM_H>
__global__ void k_gather(const float* __restrict__ xin, int n) {
    int v = blockIdx.x * (blockDim.x >> 5) + (threadIdx.x >> 5);
    if (v >= n) return;
    int lane = threadIdx.x & 31;
    const float* src = FROM_H ? g_h : xin;
    int p = g_off[v];
    int end = g_off[v + 1];
    float4 a0 = make_float4(0.f, 0.f, 0.f, 0.f);
    float4 a1 = make_float4(0.f, 0.f, 0.f, 0.f);
    for (; p + 3 < end; p += 4) {
        int u0 = g_csrc[p], u1 = g_csrc[p + 1], u2 = g_csrc[p + 2], u3 = g_csrc[p + 3];
        float s0 = g_degO[u0], s1 = g_degO[u1], s2 = g_degO[u2], s3 = g_degO[u3];
        float4 a = reinterpret_cast<const float4*>(src + (size_t)u0 * D)[lane];
        float4 b = reinterpret_cast<const float4*>(src + (size_t)u1 * D)[lane];
        float4 c = reinterpret_cast<const float4*>(src + (size_t)u2 * D)[lane];
        float4 d = reinterpret_cast<const float4*>(src + (size_t)u3 * D)[lane];
        a0.x += a.x * s0; a0.y += a.y * s0; a0.z += a.z * s0; a0.w += a.w * s0;
        a1.x += b.x * s1; a1.y += b.y * s1; a1.z += b.z * s1; a1.w += b.w * s1;
        a0.x += c.x * s2; a0.y += c.y * s2; a0.z += c.z * s2; a0.w += c.w * s2;
        a1.x += d.x * s3; a1.y += d.y * s3; a1.z += d.z * s3; a1.w += d.w * s3;
    }
    for (; p < end; p++) {
        int u0 = g_csrc[p];
        float s0 = g_degO[u0];
        float4 a = reinterpret_cast<const float4*>(src + (size_t)u0 * D)[lane];
        a0.x += a.x * s0; a0.y += a.y * s0; a0.z += a.z * s0; a0.w += a.w * s0;
    }
    a0.x += a1.x; a0.y += a1.y; a0.z += a1.z; a0.w += a1.w;

    __nv_bfloat162 h0 = __float22bfloat162_rn(make_float2(a0.x, a0.y));
    __nv_bfloat162 h1 = __float22bfloat162_rn(make_float2(a0.z, a0.w));
    __nv_bfloat162 l0 = __float22bfloat162_rn(make_float2(a0.x - __bfloat162float(h0.x),
                                                          a0.y - __bfloat162float(h0.y)));
    __nv_bfloat162 l1 = __float22bfloat162_rn(make_float2(a0.z - __bfloat162float(h1.x),
                                                          a0.w - __bfloat162float(h1.y)));
    uint2 hv = make_uint2(*reinterpret_cast<uint32_t*>(&h0), *reinterpret_cast<uint32_t*>(&h1));
    uint2 lv = make_uint2(*reinterpret_cast<uint32_t*>(&l0), *reinterpret_cast<uint32_t*>(&l1));
    reinterpret_cast<uint2*>(g_ahi + (size_t)v * 64)[lane] = hv;
    reinterpret_cast<uint2*>(g_alo + (size_t)v * 64)[lane] = lv;
}

// ================= bf16 split-3 MMA GEMM with ldmatrix fragments =================
__device__ __forceinline__ void mma_bf16(float* d, const uint32_t* a,
                                         uint32_t b0, uint32_t b1) {
    asm volatile(
        "mma.sync.aligned.m16n8k16.row.col.f32.bf16.bf16.f32 "
        "{%0,%1,%2,%3}, {%4,%5,%6,%7}, {%8,%9}, {%0,%1,%2,%3};"
        : "+f"(d[0]), "+f"(d[1]), "+f"(d[2]), "+f"(d[3])
        : "r"(a[0]), "r"(a[1]), "r"(a[2]), "r"(a[3]), "r"(b0), "r"(b1));
}
__device__ __forceinline__ void ldsm_x4(uint32_t* r, uint32_t addr) {
    asm volatile("ldmatrix.sync.aligned.m8n8.x4.shared.b16 {%0,%1,%2,%3}, [%4];"
                 : "=r"(r[0]), "=r"(r[1]), "=r"(r[2]), "=r"(r[3]) : "r"(addr));
}

// smem: Ahi(64x68) Alo(64x68) Whi(128x68) Wlo(128x68) u32 = 104448 B -> 2 CTA/SM
#define SMEM_MMA ((2 * 64 * PITCH + 2 * 128 * PITCH) * 4)

template <bool LAYER1>
__global__ __launch_bounds__(512, 2)
void k_gemm_mma(const float* __restrict__ bias,
                const float* __restrict__ xres, float* __restrict__ outp, int n) {
    extern __shared__ uint32_t sm[];
    uint32_t* Ahi = sm;
    uint32_t* Alo = sm + 64 * PITCH;
    uint32_t* Whi = sm + 2 * 64 * PITCH;
    uint32_t* Wlo = Whi + 128 * PITCH;

    const uint32_t* whi = LAYER1 ? g_w1hi : g_w2hi;
    const uint32_t* wlo = LAYER1 ? g_w1lo : g_w2lo;

    const int tid = threadIdx.x;
    const int warp = tid >> 5;
    const int lane = tid & 31;
    const int g = lane >> 2;
    const int t = lane & 3;
    const int p = warp & 7;        // n-pair (16 cols)
    const int mh = warp >> 3;      // m-half (32 rows)
    float* out = LAYER1 ? g_h : outp;

    // ldmatrix lane addressing: lanes 0-15 -> rows 0-15, lanes 16-31 -> +16B (4 u32)
    const int lr = lane & 15;           // row within 16-row tile
    const int lh = (lane >> 4) * 4;     // u32 offset for k-half
    const uint32_t sAhi = (uint32_t)__cvta_generic_to_shared(Ahi);
    const uint32_t sAlo = (uint32_t)__cvta_generic_to_shared(Alo);
    const uint32_t sWhi = (uint32_t)__cvta_generic_to_shared(Whi);
    const uint32_t sWlo = (uint32_t)__cvta_generic_to_shared(Wlo);
    // B tile rows for this warp: p*16 + lr  (covers both n-tiles in one x4)
    const uint32_t bRowOff = (uint32_t)((p * 16 + lr) * PITCH + lh) * 4u;

    // ---- W fill once: 128 rows x 16 uint4, hi+lo ----
#pragma unroll
    for (int it = 0; it < 4; it++) {
        int idx = tid + it * 512;            // 0..2047
        int r = idx >> 4, c = idx & 15;
        *reinterpret_cast<uint4*>(Whi + r * PITCH + c * 4) =
            reinterpret_cast<const uint4*>(whi + r * 64)[c];
        *reinterpret_cast<uint4*>(Wlo + r * PITCH + c * 4) =
            reinterpret_cast<const uint4*>(wlo + r * 64)[c];
    }

    // ---- two 64-row tiles per CTA ----
#pragma unroll
    for (int tile = 0; tile < 2; tile++) {
        const int rowBase = blockIdx.x * 128 + tile * 64;

        // A fill: 64 rows x 16 uint4, hi+lo
#pragma unroll
        for (int it = 0; it < 2; it++) {
            int idx = tid + it * 512;        // 0..1023
            int r = idx >> 4, c = idx & 15;
            int grow = rowBase + r;
            uint4 vh = make_uint4(0u, 0u, 0u, 0u), vl = vh;
            if (grow < n) {
                vh = reinterpret_cast<const uint4*>(g_ahi + (size_t)grow * 64)[c];
                vl = reinterpret_cast<const uint4*>(g_alo + (size_t)grow * 64)[c];
            }
            *reinterpret_cast<uint4*>(Ahi + r * PITCH + c * 4) = vh;
            *reinterpret_cast<uint4*>(Alo + r * PITCH + c * 4) = vl;
        }
        __syncthreads();

        float acc[2][2][4];
#pragma unroll
        for (int mt = 0; mt < 2; mt++)
#pragma unroll
            for (int nt = 0; nt < 2; nt++)
#pragma unroll
                for (int q = 0; q < 4; q++) acc[mt][nt][q] = 0.f;

#pragma unroll
        for (int kt = 0; kt < 8; kt++) {
            const uint32_t kb4 = (uint32_t)(kt * 8) * 4u;  // byte offset of k-tile
            // B fragments: one x4 covers both n-tiles, regs = [nt0b0, nt1b0, nt0b1, nt1b1]
            uint32_t bh[4], bl[4];
            ldsm_x4(bh, sWhi + bRowOff + kb4);
            ldsm_x4(bl, sWlo + bRowOff + kb4);
#pragma unroll
            for (int mt = 0; mt < 2; mt++) {
                const uint32_t aOff =
                    (uint32_t)((mh * 32 + mt * 16 + lr) * PITCH + lh) * 4u + kb4;
                uint32_t ah[4], al[4];
                ldsm_x4(ah, sAhi + aOff);
                ldsm_x4(al, sAlo + aOff);
#pragma unroll
                for (int nt = 0; nt < 2; nt++) {
                    mma_bf16(acc[mt][nt], ah, bh[nt], bh[2 + nt]);   // hi*hi
                    mma_bf16(acc[mt][nt], al, bh[nt], bh[2 + nt]);   // lo*hi
                    mma_bf16(acc[mt][nt], ah, bl[nt], bl[2 + nt]);   // hi*lo
                }
            }
        }
        __syncthreads();   // A-tile fully consumed before next fill

        // epilogue for this tile
#pragma unroll
        for (int nt = 0; nt < 2; nt++) {
            int col = p * 16 + nt * 8 + 2 * t;
            float2 b2 = *reinterpret_cast<const float2*>(bias + col);
#pragma unroll
            for (int mt = 0; mt < 2; mt++) {
                int r0 = rowBase + mh * 32 + mt * 16 + g;
                int r1 = r0 + 8;
                if (r0 < n) {
                    float inv = g_degI[r0];
                    float o0 = (acc[mt][nt][0] + b2.x) * inv;
                    float o1 = (acc[mt][nt][1] + b2.y) * inv;
                    if (LAYER1) {
                        float2 x2 = *reinterpret_cast<const float2*>(xres + (size_t)r0 * D + col);
                        o0 = fmaxf(o0 + x2.x, 0.f);
                        o1 = fmaxf(o1 + x2.y, 0.f);
                    }
                    *reinterpret_cast<float2*>(out + (size_t)r0 * D + col) = make_float2(o0, o1);
                }
                if (r1 < n) {
                    float inv = g_degI[r1];
                    float o0 = (acc[mt][nt][2] + b2.x) * inv;
                    float o1 = (acc[mt][nt][3] + b2.y) * inv;
                    if (LAYER1) {
                        float2 x2 = *reinterpret_cast<const float2*>(xres + (size_t)r1 * D + col);
                        o0 = fmaxf(o0 + x2.x, 0.f);
                        o1 = fmaxf(o1 + x2.y, 0.f);
                    }
                    *reinterpret_cast<float2*>(out + (size_t)r1 * D + col) = make_float2(o0, o1);
                }
            }
        }
    }
}

// ---------------- launch ----------------
extern "C" void kernel_launch(void* const* d_in, const int* in_sizes, int n_in,
                              void* d_out, int out_size) {
    const float* x  = (const float*)d_in[0];
    const void*  ei = d_in[1];
    const float* W1 = (const float*)d_in[2];
    const float* b1 = (const float*)d_in[3];
    const float* W2 = (const float*)d_in[4];
    const float* b2 = (const float*)d_in[5];
    float* out      = (float*)d_out;

    const int n = in_sizes[0] / D;   // 100000
    const int E = in_sizes[1] / 2;   // 800000

    const int CB = (E + 255) / 256;
    const int FB = (n + 255) / 256;
    const int NB = (n + 255) / 256;
    const int GAB = (n + 7) / 8;
    const int GB = (n + 127) / 128;

    cudaFuncSetAttribute(k_gemm_mma<true>,  cudaFuncAttributeMaxDynamicSharedMemorySize, SMEM_MMA);
    cudaFuncSetAttribute(k_gemm_mma<false>, cudaFuncAttributeMaxDynamicSharedMemorySize, SMEM_MMA);

    // prep (6 launches)
    k_prep0<<<FB + 64, 256>>>(ei, n, FB, W1, W2);
    k_count<<<(2 * E + 255) / 256, 256>>>(ei, E);
    k_scan1<<<NB, 256>>>(n);
    k_scan2<<<1, 512>>>(NB);
    k_scan3_fin<<<NB, 256>>>(n, E);
    k_bucket<<<CB, 256>>>(ei, E);

    // layer 1: gather -> (ahi, alo); h = relu((agg@W1^T + b1)*invI + x)
    k_gather<false><<<GAB, 256>>>(x, n);
    k_gemm_mma<true><<<GB, 512, SMEM_MMA>>>(b1, x, nullptr, n);

    // layer 2: gather(h) -> (ahi, alo); out = (agg@W2^T + b2)*invI
    k_gather<true><<<GAB, 256>>>(nullptr, n);
    k_gemm_mma<false><<<GB, 512, SMEM_MMA>>>(b2, nullptr, out, n);
}

// round 13
// speedup vs baseline: 1.3140x; 1.0097x over previous
#include <cuda_runtime.h>
#include <cuda_bf16.h>
#include <cstdint>
#include <cstddef>

#define D 128
#define NMAX 100096   // multiple of 128
#define EMAX 800000
#define PITCH 68      // u32 per smem row (136 bf16): ldmatrix conflict-free

// ---------------- scratch (device globals; no allocation allowed) ----------------
__device__ __align__(128) float    g_degO[NMAX];
__device__ __align__(128) float    g_degI[NMAX];
__device__ __align__(128) int      g_cntO[NMAX];
__device__ __align__(128) int      g_cntI[NMAX];
__device__ __align__(128) int      g_off[NMAX];
__device__ __align__(128) int      g_cur[NMAX];
__device__ __align__(128) int      g_csrc[EMAX];
__device__ __align__(128) uint32_t g_ahi[(size_t)NMAX * 64];  // agg hi (packed bf16x2)
__device__ __align__(128) uint32_t g_alo[(size_t)NMAX * 64];  // agg lo
__device__ __align__(128) float    g_h[(size_t)NMAX * D];     // layer-1 output (fp32)
__device__ __align__(128) uint32_t g_w1hi[D * 64];
__device__ __align__(128) uint32_t g_w1lo[D * 64];
__device__ __align__(128) uint32_t g_w2hi[D * 64];
__device__ __align__(128) uint32_t g_w2lo[D * 64];
__device__ int g_is64;
__device__ int g_total;

// ---------------- prep0: zero counters + dtype probe + W split (one grid) --------
__global__ void k_prep0(const void* __restrict__ ei, int n, int FB,
                        const float* __restrict__ W1, const float* __restrict__ W2) {
    if (blockIdx.x < (unsigned)FB) {
        int i = blockIdx.x * blockDim.x + threadIdx.x;
        if (i < n) { g_cntO[i] = 0; g_cntI[i] = 0; }
        if (blockIdx.x == 0 && threadIdx.x == 0) {
            const long long* e64 = (const long long*)ei;
            int ok = 1;
            for (int k = 0; k < 16; k++) {
                long long v = e64[k];
                if (v < 0 || v >= (long long)n) ok = 0;
            }
            g_is64 = ok;   // int32 read as int64 packs random high word -> out of range
            g_total = 0;
        }
    } else {
        int i = (blockIdx.x - FB) * blockDim.x + threadIdx.x;  // 0..16383
        if (i >= 2 * D * 64) return;
        int which = i >= D * 64;
        int idx = which ? i - D * 64 : i;
        const float* W = which ? W2 : W1;
        float2 v = reinterpret_cast<const float2*>(W)[idx];
        __nv_bfloat162 h = __float22bfloat162_rn(make_float2(v.x, v.y));
        float lx = v.x - __bfloat162float(h.x);
        float ly = v.y - __bfloat162float(h.y);
        __nv_bfloat162 l = __float22bfloat162_rn(make_float2(lx, ly));
        uint32_t* hi = which ? g_w2hi : g_w1hi;
        uint32_t* lo = which ? g_w2lo : g_w1lo;
        hi[idx] = *reinterpret_cast<uint32_t*>(&h);
        lo[idx] = *reinterpret_cast<uint32_t*>(&l);
    }
}

// ---------------- degree count: 4 edges per thread, vectorized ----------------
__global__ void k_count(const void* __restrict__ ei, int E) {
    int q = blockIdx.x * blockDim.x + threadIdx.x;   // quad index over 2E
    int base = q * 4;
    if (base >= 2 * E) return;
    int v[4];
    int nv = min(4, 2 * E - base);
    if (g_is64) {
        const long long* e64 = (const long long*)ei;
        longlong2 p0 = *reinterpret_cast<const longlong2*>(e64 + base);
        v[0] = (int)p0.x; v[1] = (int)p0.y;
        if (nv > 2) {
            longlong2 p1 = *reinterpret_cast<const longlong2*>(e64 + base + 2);
            v[2] = (int)p1.x; v[3] = (int)p1.y;
        }
    } else {
        int4 p = *reinterpret_cast<const int4*>((const int*)ei + base);
        v[0] = p.x; v[1] = p.y; v[2] = p.z; v[3] = p.w;
    }
#pragma unroll
    for (int k = 0; k < 4; k++) {
        if (k >= nv) break;
        int i = base + k;
        if (i < E) atomicAdd(&g_cntO[v[k]], 1);
        else       atomicAdd(&g_cntI[v[k]], 1);
    }
}

// ---------------- alloc: fused block-scan offset allocation + degree finalize ----
// bucket ORDER in g_csrc is arbitrary (atomic block-base grab); gather only needs
// [off, off+cnt) per node.
__global__ void k_alloc(int n) {
    __shared__ int s[256];
    __shared__ int base;
    int i = blockIdx.x * 256 + threadIdx.x;
    int c = (i < n) ? g_cntI[i] : 0;
    s[threadIdx.x] = c;
    __syncthreads();
#pragma unroll
    for (int off = 1; off < 256; off <<= 1) {
        int t = (threadIdx.x >= off) ? s[threadIdx.x - off] : 0;
        __syncthreads();
        s[threadIdx.x] += t;
        __syncthreads();
    }
    if (threadIdx.x == 255) base = atomicAdd(&g_total, s[255]);
    __syncthreads();
    if (i < n) {
        int off = base + s[threadIdx.x] - c;   // exclusive within block + block base
        g_off[i] = off;
        g_cur[i] = off;
        g_degO[i] = rsqrtf((float)max(g_cntO[i], 1));
        g_degI[i] = rsqrtf((float)max(g_cntI[i], 1));
    }
}

// ---------------- bucket: 2 edges per thread, vectorized ----------------
__global__ void k_bucket(const void* __restrict__ ei, int E) {
    int q = blockIdx.x * blockDim.x + threadIdx.x;
    int base = q * 2;
    if (base >= E) return;
    int r[2], c[2];
    int nv = min(2, E - base);
    if (g_is64) {
        const long long* e64 = (const long long*)ei;
        longlong2 pr = *reinterpret_cast<const longlong2*>(e64 + base);
        longlong2 pc = *reinterpret_cast<const longlong2*>(e64 + E + base);
        r[0] = (int)pr.x; r[1] = (int)pr.y;
        c[0] = (int)pc.x; c[1] = (int)pc.y;
    } else {
        int2 pr = *reinterpret_cast<const int2*>((const int*)ei + base);
        int2 pc = *reinterpret_cast<const int2*>((const int*)ei + E + base);
        r[0] = pr.x; r[1] = pr.y;
        c[0] = pc.x; c[1] = pc.y;
    }
#pragma unroll
    for (int k = 0; k < 2; k++) {
        if (k >= nv) break;
        int pos = atomicAdd(&g_cur[c[k]], 1);
        g_csrc[pos] = r[k];
    }
}

// ---------------- gather: agg[v] = sum src[u]*invO[u]; writes bf16 hi/lo ----------
template <bool FROM_H>
__global__ void k_gather(const float* __restrict__ xin, int n) {
    int v = blockIdx.x * (blockDim.x >> 5) + (threadIdx.x >> 5);
    if (v >= n) return;
    int lane = threadIdx.x & 31;
    const float* src = FROM_H ? g_h : xin;
    int p = g_off[v];
    int end = p + g_cntI[v];
    float4 a0 = make_float4(0.f, 0.f, 0.f, 0.f);
    float4 a1 = make_float4(0.f, 0.f, 0.f, 0.f);
    for (; p + 3 < end; p += 4) {
        int u0 = g_csrc[p], u1 = g_csrc[p + 1], u2 = g_csrc[p + 2], u3 = g_csrc[p + 3];
        float s0 = g_degO[u0], s1 = g_degO[u1], s2 = g_degO[u2], s3 = g_degO[u3];
        float4 a = reinterpret_cast<const float4*>(src + (size_t)u0 * D)[lane];
        float4 b = reinterpret_cast<const float4*>(src + (size_t)u1 * D)[lane];
        float4 c = reinterpret_cast<const float4*>(src + (size_t)u2 * D)[lane];
        float4 d = reinterpret_cast<const float4*>(src + (size_t)u3 * D)[lane];
        a0.x += a.x * s0; a0.y += a.y * s0; a0.z += a.z * s0; a0.w += a.w * s0;
        a1.x += b.x * s1; a1.y += b.y * s1; a1.z += b.z * s1; a1.w += b.w * s1;
        a0.x += c.x * s2; a0.y += c.y * s2; a0.z += c.z * s2; a0.w += c.w * s2;
        a1.x += d.x * s3; a1.y += d.y * s3; a1.z += d.z * s3; a1.w += d.w * s3;
    }
    for (; p < end; p++) {
        int u0 = g_csrc[p];
        float s0 = g_degO[u0];
        float4 a = reinterpret_cast<const float4*>(src + (size_t)u0 * D)[lane];
        a0.x += a.x * s0; a0.y += a.y * s0; a0.z += a.z * s0; a0.w += a.w * s0;
    }
    a0.x += a1.x; a0.y += a1.y; a0.z += a1.z; a0.w += a1.w;

    __nv_bfloat162 h0 = __float22bfloat162_rn(make_float2(a0.x, a0.y));
    __nv_bfloat162 h1 = __float22bfloat162_rn(make_float2(a0.z, a0.w));
    __nv_bfloat162 l0 = __float22bfloat162_rn(make_float2(a0.x - __bfloat162float(h0.x),
                                                          a0.y - __bfloat162float(h0.y)));
    __nv_bfloat162 l1 = __float22bfloat162_rn(make_float2(a0.z - __bfloat162float(h1.x),
                                                          a0.w - __bfloat162float(h1.y)));
    uint2 hv = make_uint2(*reinterpret_cast<uint32_t*>(&h0), *reinterpret_cast<uint32_t*>(&h1));
    uint2 lv = make_uint2(*reinterpret_cast<uint32_t*>(&l0), *reinterpret_cast<uint32_t*>(&l1));
    reinterpret_cast<uint2*>(g_ahi + (size_t)v * 64)[lane] = hv;
    reinterpret_cast<uint2*>(g_alo + (size_t)v * 64)[lane] = lv;
}

// ================= bf16 split-3 MMA GEMM with ldmatrix fragments =================
__device__ __forceinline__ void mma_bf16(float* d, const uint32_t* a,
                                         uint32_t b0, uint32_t b1) {
    asm volatile(
        "mma.sync.aligned.m16n8k16.row.col.f32.bf16.bf16.f32 "
        "{%0,%1,%2,%3}, {%4,%5,%6,%7}, {%8,%9}, {%0,%1,%2,%3};"
        : "+f"(d[0]), "+f"(d[1]), "+f"(d[2]), "+f"(d[3])
        : "r"(a[0]), "r"(a[1]), "r"(a[2]), "r"(a[3]), "r"(b0), "r"(b1));
}
__device__ __forceinline__ void ldsm_x4(uint32_t* r, uint32_t addr) {
    asm volatile("ldmatrix.sync.aligned.m8n8.x4.shared.b16 {%0,%1,%2,%3}, [%4];"
                 : "=r"(r[0]), "=r"(r[1]), "=r"(r[2]), "=r"(r[3]) : "r"(addr));
}

// smem: Ahi(64x68) Alo(64x68) Whi(128x68) Wlo(128x68) u32 = 104448 B -> 2 CTA/SM
#define SMEM_MMA ((2 * 64 * PITCH + 2 * 128 * PITCH) * 4)

template <bool LAYER1>
__global__ __launch_bounds__(512, 2)
void k_gemm_mma(const float* __restrict__ bias,
                const float* __restrict__ xres, float* __restrict__ outp, int n) {
    extern __shared__ uint32_t sm[];
    uint32_t* Ahi = sm;
    uint32_t* Alo = sm + 64 * PITCH;
    uint32_t* Whi = sm + 2 * 64 * PITCH;
    uint32_t* Wlo = Whi + 128 * PITCH;

    const uint32_t* whi = LAYER1 ? g_w1hi : g_w2hi;
    const uint32_t* wlo = LAYER1 ? g_w1lo : g_w2lo;

    const int tid = threadIdx.x;
    const int warp = tid >> 5;
    const int lane = tid & 31;
    const int g = lane >> 2;
    const int t = lane & 3;
    const int p = warp & 7;        // n-pair (16 cols)
    const int mh = warp >> 3;      // m-half (32 rows)
    float* out = LAYER1 ? g_h : outp;

    const int lr = lane & 15;
    const int lh = (lane >> 4) * 4;
    const uint32_t sAhi = (uint32_t)__cvta_generic_to_shared(Ahi);
    const uint32_t sAlo = (uint32_t)__cvta_generic_to_shared(Alo);
    const uint32_t sWhi = (uint32_t)__cvta_generic_to_shared(Whi);
    const uint32_t sWlo = (uint32_t)__cvta_generic_to_shared(Wlo);
    const uint32_t bRowOff = (uint32_t)((p * 16 + lr) * PITCH + lh) * 4u;

    // ---- W fill once: 128 rows x 16 uint4, hi+lo ----
#pragma unroll
    for (int it = 0; it < 4; it++) {
        int idx = tid + it * 512;            // 0..2047
        int r = idx >> 4, c = idx & 15;
        *reinterpret_cast<uint4*>(Whi + r * PITCH + c * 4) =
            reinterpret_cast<const uint4*>(whi + r * 64)[c];
        *reinterpret_cast<uint4*>(Wlo + r * PITCH + c * 4) =
            reinterpret_cast<const uint4*>(wlo + r * 64)[c];
    }

    // ---- two 64-row tiles per CTA ----
#pragma unroll
    for (int tile = 0; tile < 2; tile++) {
        const int rowBase = blockIdx.x * 128 + tile * 64;

        // A fill: 64 rows x 16 uint4, hi+lo
#pragma unroll
        for (int it = 0; it < 2; it++) {
            int idx = tid + it * 512;        // 0..1023
            int r = idx >> 4, c = idx & 15;
            int grow = rowBase + r;
            uint4 vh = make_uint4(0u, 0u, 0u, 0u), vl = vh;
            if (grow < n) {
                vh = reinterpret_cast<const uint4*>(g_ahi + (size_t)grow * 64)[c];
                vl = reinterpret_cast<const uint4*>(g_alo + (size_t)grow * 64)[c];
            }
            *reinterpret_cast<uint4*>(Ahi + r * PITCH + c * 4) = vh;
            *reinterpret_cast<uint4*>(Alo + r * PITCH + c * 4) = vl;
        }
        __syncthreads();

        float acc[2][2][4];
#pragma unroll
        for (int mt = 0; mt < 2; mt++)
#pragma unroll
            for (int nt = 0; nt < 2; nt++)
#pragma unroll
                for (int q = 0; q < 4; q++) acc[mt][nt][q] = 0.f;

#pragma unroll
        for (int kt = 0; kt < 8; kt++) {
            const uint32_t kb4 = (uint32_t)(kt * 8) * 4u;
            uint32_t bh[4], bl[4];
            ldsm_x4(bh, sWhi + bRowOff + kb4);
            ldsm_x4(bl, sWlo + bRowOff + kb4);
#pragma unroll
            for (int mt = 0; mt < 2; mt++) {
                const uint32_t aOff =
                    (uint32_t)((mh * 32 + mt * 16 + lr) * PITCH + lh) * 4u + kb4;
                uint32_t ah[4], al[4];
                ldsm_x4(ah, sAhi + aOff);
                ldsm_x4(al, sAlo + aOff);
#pragma unroll
                for (int nt = 0; nt < 2; nt++) {
                    mma_bf16(acc[mt][nt], ah, bh[nt], bh[2 + nt]);   // hi*hi
                    mma_bf16(acc[mt][nt], al, bh[nt], bh[2 + nt]);   // lo*hi
                    mma_bf16(acc[mt][nt], ah, bl[nt], bl[2 + nt]);   // hi*lo
                }
            }
        }
        __syncthreads();

        // epilogue for this tile
#pragma unroll
        for (int nt = 0; nt < 2; nt++) {
            int col = p * 16 + nt * 8 + 2 * t;
            float2 b2 = *reinterpret_cast<const float2*>(bias + col);
#pragma unroll
            for (int mt = 0; mt < 2; mt++) {
                int r0 = rowBase + mh * 32 + mt * 16 + g;
                int r1 = r0 + 8;
                if (r0 < n) {
                    float inv = g_degI[r0];
                    float o0 = (acc[mt][nt][0] + b2.x) * inv;
                    float o1 = (acc[mt][nt][1] + b2.y) * inv;
                    if (LAYER1) {
                        float2 x2 = *reinterpret_cast<const float2*>(xres + (size_t)r0 * D + col);
                        o0 = fmaxf(o0 + x2.x, 0.f);
                        o1 = fmaxf(o1 + x2.y, 0.f);
                    }
                    *reinterpret_cast<float2*>(out + (size_t)r0 * D + col) = make_float2(o0, o1);
                }
                if (r1 < n) {
                    float inv = g_degI[r1];
                    float o0 = (acc[mt][nt][2] + b2.x) * inv;
                    float o1 = (acc[mt][nt][3] + b2.y) * inv;
                    if (LAYER1) {
                        float2 x2 = *reinterpret_cast<const float2*>(xres + (size_t)r1 * D + col);
                        o0 = fmaxf(o0 + x2.x, 0.f);
                        o1 = fmaxf(o1 + x2.y, 0.f);
                    }
                    *reinterpret_cast<float2*>(out + (size_t)r1 * D + col) = make_float2(o0, o1);
                }
            }
        }
    }
}

// ---------------- launch ----------------
extern "C" void kernel_launch(void* const* d_in, const int* in_sizes, int n_in,
                              void* d_out, int out_size) {
    const float* x  = (const float*)d_in[0];
    const void*  ei = d_in[1];
    const float* W1 = (const float*)d_in[2];
    const float* b1 = (const float*)d_in[3];
    const float* W2 = (const float*)d_in[4];
    const float* b2 = (const float*)d_in[5];
    float* out      = (float*)d_out;

    const int n = in_sizes[0] / D;   // 100000
    const int E = in_sizes[1] / 2;   // 800000

    const int FB = (n + 255) / 256;
    const int NB = (n + 255) / 256;
    const int GAB = (n + 7) / 8;
    const int GB = (n + 127) / 128;

    cudaFuncSetAttribute(k_gemm_mma<true>,  cudaFuncAttributeMaxDynamicSharedMemorySize, SMEM_MMA);
    cudaFuncSetAttribute(k_gemm_mma<false>, cudaFuncAttributeMaxDynamicSharedMemorySize, SMEM_MMA);

    // prep (4 launches)
    k_prep0<<<FB + 64, 256>>>(ei, n, FB, W1, W2);
    k_count<<<(2 * E / 4 + 255) / 256, 256>>>(ei, E);
    k_alloc<<<NB, 256>>>(n);
    k_bucket<<<(E / 2 + 255) / 256, 256>>>(ei, E);

    // layer 1: gather -> (ahi, alo); h = relu((agg@W1^T + b1)*invI + x)
    k_gather<false><<<GAB, 256>>>(x, n);
    k_gemm_mma<true><<<GB, 512, SMEM_MMA>>>(b1, x, nullptr, n);

    // layer 2: gather(h) -> (ahi, alo); out = (agg@W2^T + b2)*invI
    k_gather<true><<<GAB, 256>>>(nullptr, n);
    k_gemm_mma<false><<<GB, 512, SMEM_MMA>>>(b2, nullptr, out, n);
}